// round 7
// baseline (speedup 1.0000x reference)
#include <cuda_runtime.h>
#include <cstdint>
#include <cstddef>

#define B 32
#define T 512
#define D 500
#define H 10
#define HD 50
#define D3 1500
#define BT (B*T)
#define BTD (BT*D)
#define KW 7
#define QKVP 1920   // padded qkv row pitch: 3 * H * 64

// ---------------- scratch (static device arrays; no runtime allocation) ----
__device__ float g_b0[BTD];
__device__ float g_b1[BTD];
__device__ float g_b2[BTD];
__device__ float g_bt[BTD];
__device__ float g_b1t[BTD];
__device__ float g_b2t[BTD];
__device__ float g_qkv[(size_t)BT * QKVP];
__device__ float g_wt[6 * D * D + D3 * D];

// ---------------- helpers ---------------------------------------------------
__device__ __forceinline__ uint32_t f2tf32(float x) {
    uint32_t r;
    asm("cvt.rna.tf32.f32 %0, %1;" : "=r"(r) : "f"(x));
    return r;
}
__device__ __forceinline__ uint32_t smem_u32(const void* p) {
    uint32_t a;
    asm("{ .reg .u64 t; cvta.to.shared.u64 t, %1; cvt.u32.u64 %0, t; }" : "=r"(a) : "l"(p));
    return a;
}

#define MMA_TF32(c, a, b) \
    asm volatile("mma.sync.aligned.m16n8k8.row.col.f32.tf32.tf32.f32 " \
        "{%0,%1,%2,%3}, {%4,%5,%6,%7}, {%8,%9}, {%0,%1,%2,%3};" \
        : "+f"((c)[0]), "+f"((c)[1]), "+f"((c)[2]), "+f"((c)[3]) \
        : "r"((a)[0]), "r"((a)[1]), "r"((a)[2]), "r"((a)[3]), \
          "r"((b)[0]), "r"((b)[1]))

// ldmatrix on 32-bit tf32 data via b16 row-address trick
#define LDSM4(r, addr) \
    asm volatile("ldmatrix.sync.aligned.m8n8.x4.shared.b16 {%0,%1,%2,%3}, [%4];" \
        : "=r"((r)[0]), "=r"((r)[1]), "=r"((r)[2]), "=r"((r)[3]) : "r"(addr))
#define LDSM2(r0, r1, addr) \
    asm volatile("ldmatrix.sync.aligned.m8n8.x2.shared.b16 {%0,%1}, [%2];" \
        : "=r"(r0), "=r"(r1) : "r"(addr))

#define CP16(dst, src) \
    asm volatile("cp.async.ca.shared.global [%0], [%1], 16;" :: "r"(dst), "l"(src) : "memory")
#define CP8(dst, src) \
    asm volatile("cp.async.ca.shared.global [%0], [%1], 8;"  :: "r"(dst), "l"(src) : "memory")
#define CP16P(dst, src, p) \
    asm volatile("cp.async.ca.shared.global [%0], [%1], 16, %2;" :: "r"(dst), "l"(src), "r"(p) : "memory")
#define CPCOMMIT() asm volatile("cp.async.commit_group;" ::: "memory")
#define CPWAIT0()  asm volatile("cp.async.wait_group 0;" ::: "memory")
#define CPWAIT1()  asm volatile("cp.async.wait_group 1;" ::: "memory")

// ---------------- merged weight tf32 pre-round -----------------------------
__global__ void cvt_all(const float* __restrict__ p0, const float* __restrict__ p1,
                        const float* __restrict__ p2, const float* __restrict__ p3,
                        const float* __restrict__ p4, const float* __restrict__ p5,
                        const float* __restrict__ p6, uint32_t* __restrict__ o) {
    const int DD = D * D;
    int i = blockIdx.x * blockDim.x + threadIdx.x;
    if (i >= 6 * DD + D3 * D) return;
    float v;
    if      (i < DD)              v = p0[i];
    else if (i < 2 * DD)          v = p1[i - DD];
    else if (i < 3 * DD)          v = p2[i - 2 * DD];
    else if (i < 4 * DD)          v = p3[i - 3 * DD];
    else if (i < 4 * DD + D3 * D) v = p4[i - 4 * DD];
    else if (i < 5 * DD + D3 * D) v = p5[i - 4 * DD - D3 * D];
    else                          v = p6[i - 5 * DD - D3 * D];
    o[i] = f2tf32(v);
}

// ---------------- positional embedding + add ------------------------------
__global__ void posemb_kernel(const int* __restrict__ ori,
                              const float* __restrict__ x,
                              float* __restrict__ out) {
    int idx = blockIdx.x * blockDim.x + threadIdx.x;
    if (idx >= BTD) return;
    int d  = idx % D;
    int bt = idx / D;
    int t  = bt % T;
    float pe = 0.f;
    if (ori[bt] != 0) {
        float pos = (float)(t + 1);
        int   i   = (d < 250) ? d : (d - 250);
        float ang = pos * expf((float)i * -0.036989318763f);
        pe = (d < 250) ? sinf(ang) : cosf(ang);
    }
    out[idx] = pe + x[idx];
}

// ---------------- depthwise conv1d (k=7, pad=3), float4, tf32-rounded out --
__global__ void dwconv4_kernel(const float* __restrict__ x,
                               const float* __restrict__ w,
                               const float* __restrict__ bias,
                               uint32_t* __restrict__ y) {
    int idx = blockIdx.x * blockDim.x + threadIdx.x;
    if (idx >= BTD / 4) return;
    int d4 = idx % (D / 4);
    int bt = idx / (D / 4);
    int t  = bt % T;
    int b  = bt / T;
    int d  = d4 * 4;
    float4 bv = *(const float4*)(bias + d);
    float a0 = bv.x, a1 = bv.y, a2 = bv.z, a3 = bv.w;
    const float* xb = x + (size_t)(b * T) * D + d;
#pragma unroll
    for (int j = 0; j < KW; j++) {
        int tt = t + j - 3;
        if (tt >= 0 && tt < T) {
            float4 v = *(const float4*)(xb + (size_t)tt * D);
            a0 = fmaf(w[(d + 0) * KW + j], v.x, a0);
            a1 = fmaf(w[(d + 1) * KW + j], v.y, a1);
            a2 = fmaf(w[(d + 2) * KW + j], v.z, a2);
            a3 = fmaf(w[(d + 3) * KW + j], v.w, a3);
        }
    }
    *(uint4*)(y + (size_t)idx * 4) =
        make_uint4(f2tf32(a0), f2tf32(a1), f2tf32(a2), f2tf32(a3));
}

// =================== 3-stage pipelined tf32 warp-mma GEMM ===================
// modes: 0 = C fp32 (+res); 1 = + Ct tf32-rounded copy; 2 = head-padded qkv
#define GBM 128
#define GBN 128
#define GBK 32
#define SPITCH 36
#define GBUF ((GBM + GBN) * SPITCH)
#define GSM_BYTES (3 * GBUF * 4)

__global__ __launch_bounds__(256, 2)
void gemm_pipe(const float* __restrict__ A, const float* __restrict__ W,
               const float* __restrict__ bias, const float* __restrict__ res,
               float* __restrict__ C, uint32_t* __restrict__ Ct,
               int N, int Kd, int mode) {
    extern __shared__ uint32_t sm[];

    int tid  = threadIdx.x;
    int lane = tid & 31, wid = tid >> 5;
    int g = lane >> 2, t = lane & 3;
    int m0 = blockIdx.y * GBM;
    int n0 = blockIdx.x * GBN;
    int wm = (wid & 1) * 64;
    int wn = (wid >> 1) * 32;

    int r0 = tid >> 3, kg = tid & 7;
    uint32_t smbase = smem_u32(sm);

    // staging sources / dest offsets (within a stage)
    uint32_t adstoff[4], bdstoff[4];
    const float* asrc[4];
    const float* bsrc[4];
    uint32_t bok[4];
#pragma unroll
    for (int i = 0; i < 4; i++) {
        int r = r0 + i * 32;
        adstoff[i] = (uint32_t)(r * SPITCH + kg * 4) * 4;
        bdstoff[i] = adstoff[i] + GBM * SPITCH * 4;
        asrc[i] = A + (size_t)(m0 + r) * Kd + kg * 4;
        int n = n0 + r;
        bok[i] = (n < N) ? 16u : 0u;
        bsrc[i] = W + (size_t)((n < N) ? n : 0) * Kd + kg * 4;
    }

    // ldmatrix per-thread address components (bytes within stage)
    uint32_t aoff = ((uint32_t)((lane & 15) * SPITCH + (lane >> 4) * 4)) * 4;
    uint32_t boff = ((uint32_t)(((lane >> 4) * 8 + (lane & 7)) * SPITCH
                                + ((lane >> 3) & 1) * 4)) * 4
                    + GBM * SPITCH * 4;

    float acc[4][4][4];
#pragma unroll
    for (int mt = 0; mt < 4; mt++)
#pragma unroll
        for (int nt = 0; nt < 4; nt++)
#pragma unroll
            for (int i = 0; i < 4; i++) acc[mt][nt][i] = 0.f;

    const int KT = (Kd + GBK - 1) / GBK;

    // copy issuer for chunk -> stage
#define ISSUE_COPY(chunk, stage)                                              \
    {                                                                         \
        int k0c = (chunk) * GBK;                                              \
        int kk_ = k0c + kg * 4;                                               \
        uint32_t kin = (kk_ < Kd) ? 16u : 0u;                                 \
        uint32_t sb_ = smbase + (uint32_t)(stage) * (GBUF * 4);               \
        _Pragma("unroll")                                                     \
        for (int i = 0; i < 4; i++) {                                         \
            const float* sa = kin ? (asrc[i] + k0c) : A;                      \
            CP16P(sb_ + adstoff[i], sa, kin);                                 \
            uint32_t bb = kin & bok[i];                                       \
            const float* sb2 = bb ? (bsrc[i] + k0c) : W;                      \
            CP16P(sb_ + bdstoff[i], sb2, bb);                                 \
        }                                                                     \
        CPCOMMIT();                                                           \
    }

    // prologue: chunks 0,1 -> stages 0,1
    ISSUE_COPY(0, 0);
    ISSUE_COPY(1, 1);

    int stage = 0;
    for (int kt = 0; kt < KT; kt++) {
        if (kt + 1 < KT) { CPWAIT1(); } else { CPWAIT0(); }
        __syncthreads();
        // prefetch chunk kt+2 (writes stage read in iter kt-1; safe after barrier)
        if (kt + 2 < KT) {
            int ns = stage + 2; if (ns >= 3) ns -= 3;
            ISSUE_COPY(kt + 2, ns);
        } else {
            CPCOMMIT();  // keep group accounting uniform
        }

        uint32_t sb = smbase + (uint32_t)stage * (GBUF * 4);
#pragma unroll
        for (int ks = 0; ks < 4; ks++) {
            uint32_t kkb = ks * 32;
            uint32_t af[4][4], bf[4][2];
#pragma unroll
            for (int mt = 0; mt < 4; mt++)
                LDSM4(af[mt], sb + aoff + (uint32_t)((wm + mt * 16) * SPITCH) * 4 + kkb);
#pragma unroll
            for (int nt2 = 0; nt2 < 2; nt2++) {
                uint32_t r[4];
                LDSM4(r, sb + boff + (uint32_t)((wn + nt2 * 16) * SPITCH) * 4 + kkb);
                bf[2 * nt2][0] = r[0]; bf[2 * nt2][1] = r[1];
                bf[2 * nt2 + 1][0] = r[2]; bf[2 * nt2 + 1][1] = r[3];
            }
#pragma unroll
            for (int mt = 0; mt < 4; mt++)
#pragma unroll
                for (int nt = 0; nt < 4; nt++)
                    MMA_TF32(acc[mt][nt], af[mt], bf[nt]);
        }
        stage++; if (stage == 3) stage = 0;
    }
#undef ISSUE_COPY

#pragma unroll
    for (int mt = 0; mt < 4; mt++) {
        int row0 = m0 + wm + mt * 16 + g;
#pragma unroll
        for (int nt = 0; nt < 4; nt++) {
            int col = n0 + wn + nt * 8 + 2 * t;
            if (col < N) {
                float2 bv = *(const float2*)(bias + col);
                float2 o0, o1;
                o0.x = acc[mt][nt][0] + bv.x;
                o0.y = acc[mt][nt][1] + bv.y;
                o1.x = acc[mt][nt][2] + bv.x;
                o1.y = acc[mt][nt][3] + bv.y;
                if (mode == 2) {
                    int which = col / 500;
                    int rem   = col - which * 500;
                    int hh    = rem / 50;
                    int dd    = rem - hh * 50;
                    size_t p0 = (size_t)row0 * QKVP + which * 640 + hh * 64 + dd;
                    size_t p1 = (size_t)(row0 + 8) * QKVP + which * 640 + hh * 64 + dd;
                    uint32_t* Cq = (uint32_t*)C;
                    *(uint2*)(Cq + p0) = make_uint2(f2tf32(o0.x), f2tf32(o0.y));
                    *(uint2*)(Cq + p1) = make_uint2(f2tf32(o1.x), f2tf32(o1.y));
                } else {
                    size_t i0 = (size_t)row0 * N + col;
                    size_t i1 = (size_t)(row0 + 8) * N + col;
                    if (res) {
                        float2 r0v = *(const float2*)(res + i0);
                        float2 r1v = *(const float2*)(res + i1);
                        o0.x += r0v.x; o0.y += r0v.y;
                        o1.x += r1v.x; o1.y += r1v.y;
                    }
                    *(float2*)(C + i0) = o0;
                    *(float2*)(C + i1) = o1;
                    if (mode == 1) {
                        *(uint2*)(Ct + i0) = make_uint2(f2tf32(o0.x), f2tf32(o0.y));
                        *(uint2*)(Ct + i1) = make_uint2(f2tf32(o1.x), f2tf32(o1.y));
                    }
                }
            }
        }
    }
}

// =================== tf32 warp-mma flash attention ==========================
#define AMQ 128
#define ANK 64
#define ADP 56
#define APQ 60
#define APV 68
#define ASM_BYTES ((AMQ*APQ + ANK*APQ + ADP*APV + AMQ*APV) * 4 + 64)

__global__ __launch_bounds__(256, 2)
void attn_mma(const float* __restrict__ qkv2,
              const unsigned char* __restrict__ mask,
              uint32_t* __restrict__ out) {
    extern __shared__ uint32_t dsm[];
    uint32_t* Qs = dsm;                    // [128][60]
    uint32_t* Ks = Qs + AMQ * APQ;         // [64][60]
    uint32_t* Vt = Ks + ANK * APQ;         // [56][68]
    uint32_t* Ps = Vt + ADP * APV;         // [128][68]
    unsigned char* msk = (unsigned char*)(Ps + AMQ * APV);

    int tid  = threadIdx.x;
    int lane = tid & 31, wid = tid >> 5;
    int g = lane >> 2, t = lane & 3;
    int bh = blockIdx.y;
    int b  = bh / H, h = bh % H;
    int q0 = blockIdx.x * AMQ;
    const float scale = 0.14142135623730951f;

    for (int i = tid; i < AMQ * 6; i += 256) Qs[(i / 6) * APQ + 50 + (i % 6)] = 0;
    for (int i = tid; i < ANK * 6; i += 256) Ks[(i / 6) * APQ + 50 + (i % 6)] = 0;
    for (int i = tid; i < 6 * APV; i += 256) Vt[(50 + i / APV) * APV + (i % APV)] = 0;

    // stage Q via cp.async
    {
        int r = tid >> 1, e = tid & 1;
        const float* src = qkv2 + (size_t)(b * T + q0 + r) * QKVP + h * 64;
        uint32_t dst = smem_u32(Qs + r * APQ);
#pragma unroll
        for (int c = e; c < 12; c += 2) CP16(dst + 16 * c, src + 4 * c);
        if (e == 0) CP8(dst + 192, src + 48);
        CPCOMMIT();
    }

    int wq = wid * 16;
    uint32_t qaddr = smem_u32(Qs) + (uint32_t)((wq + (lane & 15)) * APQ + (lane >> 4) * 4) * 4;
    uint32_t kaddr = smem_u32(Ks) + (uint32_t)(((lane >> 4) * 8 + (lane & 7)) * APQ
                                               + ((lane >> 3) & 1) * 4) * 4;
    uint32_t paddr = smem_u32(Ps) + (uint32_t)((wq + (lane & 15)) * APV + (lane >> 4) * 4) * 4;
    uint32_t vaddr = smem_u32(Vt) + (uint32_t)(((lane >> 4) * 8 + (lane & 7)) * APV
                                               + ((lane >> 3) & 1) * 4) * 4;
    uint32_t v6addr = smem_u32(Vt) + (uint32_t)((48 + (lane & 7)) * APV
                                                + ((lane >> 3) & 1) * 4) * 4;
    uint32_t* PsA = Ps + (wq + g) * APV;
    uint32_t* PsB = Ps + (wq + g + 8) * APV;

    float m0 = -1e30f, m1 = -1e30f, l0 = 0.f, l1 = 0.f;
    float oacc[7][4];
#pragma unroll
    for (int nt = 0; nt < 7; nt++)
#pragma unroll
        for (int i = 0; i < 4; i++) oacc[nt][i] = 0.f;

    for (int kt = 0; kt < T / ANK; kt++) {
        int k0 = kt * ANK;
        __syncthreads();

        {
            int j = tid >> 2, q = tid & 3;
            const float* src = qkv2 + (size_t)(b * T + k0 + j) * QKVP + 640 + h * 64;
            uint32_t dst = smem_u32(Ks + j * APQ);
            CP16(dst + 16 * q,       src + 4 * q);
            CP16(dst + 16 * (q + 4), src + 4 * (q + 4));
            CP16(dst + 16 * (q + 8), src + 4 * (q + 8));
            if (q == 3) CP8(dst + 192, src + 48);
            CPCOMMIT();
        }
        {
            int j = tid >> 2, q = tid & 3;
            const float* src = qkv2 + (size_t)(b * T + k0 + j) * QKVP + 1280 + h * 64;
#pragma unroll
            for (int p = q; p < 25; p += 4) {
                float2 v = *(const float2*)(src + 2 * p);
                Vt[(2 * p) * APV + j]     = __float_as_uint(v.x);
                Vt[(2 * p + 1) * APV + j] = __float_as_uint(v.y);
            }
        }
        if (tid < ANK) msk[tid] = mask[b * T + k0 + tid];
        CPWAIT0();
        __syncthreads();

        // ---- S = Q K^T via ldmatrix
        float sacc[8][4];
#pragma unroll
        for (int nt = 0; nt < 8; nt++)
#pragma unroll
            for (int i = 0; i < 4; i++) sacc[nt][i] = 0.f;
#pragma unroll
        for (int ks = 0; ks < 7; ks++) {
            uint32_t kkb = ks * 32;
            uint32_t af[4], bf[8][2];
            LDSM4(af, qaddr + kkb);
#pragma unroll
            for (int nt2 = 0; nt2 < 4; nt2++) {
                uint32_t r[4];
                LDSM4(r, kaddr + (uint32_t)(nt2 * 16 * APQ) * 4 + kkb);
                bf[2 * nt2][0] = r[0]; bf[2 * nt2][1] = r[1];
                bf[2 * nt2 + 1][0] = r[2]; bf[2 * nt2 + 1][1] = r[3];
            }
#pragma unroll
            for (int nt = 0; nt < 8; nt++)
                MMA_TF32(sacc[nt], af, bf[nt]);
        }

        // ---- scale + mask + online softmax
        float mx0 = -1e30f, mx1 = -1e30f;
#pragma unroll
        for (int nt = 0; nt < 8; nt++) {
            sacc[nt][0] *= scale; sacc[nt][1] *= scale;
            sacc[nt][2] *= scale; sacc[nt][3] *= scale;
            int c = nt * 8 + 2 * t;
            if (msk[c])     { sacc[nt][0] = -1e30f; sacc[nt][2] = -1e30f; }
            if (msk[c + 1]) { sacc[nt][1] = -1e30f; sacc[nt][3] = -1e30f; }
            mx0 = fmaxf(mx0, fmaxf(sacc[nt][0], sacc[nt][1]));
            mx1 = fmaxf(mx1, fmaxf(sacc[nt][2], sacc[nt][3]));
        }
        mx0 = fmaxf(mx0, __shfl_xor_sync(0xffffffffu, mx0, 1));
        mx0 = fmaxf(mx0, __shfl_xor_sync(0xffffffffu, mx0, 2));
        mx1 = fmaxf(mx1, __shfl_xor_sync(0xffffffffu, mx1, 1));
        mx1 = fmaxf(mx1, __shfl_xor_sync(0xffffffffu, mx1, 2));
        float mn0 = fmaxf(m0, mx0), mn1 = fmaxf(m1, mx1);
        float c0 = __expf(m0 - mn0), c1 = __expf(m1 - mn1);
        float s0 = 0.f, s1 = 0.f;
#pragma unroll
        for (int nt = 0; nt < 8; nt++) {
            float p00 = __expf(sacc[nt][0] - mn0);
            float p01 = __expf(sacc[nt][1] - mn0);
            float p10 = __expf(sacc[nt][2] - mn1);
            float p11 = __expf(sacc[nt][3] - mn1);
            s0 += p00 + p01;
            s1 += p10 + p11;
            int c = nt * 8 + 2 * t;
            *(uint2*)(PsA + c) = make_uint2(f2tf32(p00), f2tf32(p01));
            *(uint2*)(PsB + c) = make_uint2(f2tf32(p10), f2tf32(p11));
        }
        s0 += __shfl_xor_sync(0xffffffffu, s0, 1);
        s0 += __shfl_xor_sync(0xffffffffu, s0, 2);
        s1 += __shfl_xor_sync(0xffffffffu, s1, 1);
        s1 += __shfl_xor_sync(0xffffffffu, s1, 2);
        l0 = l0 * c0 + s0; m0 = mn0;
        l1 = l1 * c1 + s1; m1 = mn1;
#pragma unroll
        for (int nt = 0; nt < 7; nt++) {
            oacc[nt][0] *= c0; oacc[nt][1] *= c0;
            oacc[nt][2] *= c1; oacc[nt][3] *= c1;
        }
        __syncwarp();

        // ---- O += P V via ldmatrix
#pragma unroll
        for (int ks = 0; ks < 8; ks++) {
            uint32_t kkb = ks * 32;
            uint32_t af[4], bf[7][2];
            LDSM4(af, paddr + kkb);
#pragma unroll
            for (int nt2 = 0; nt2 < 3; nt2++) {
                uint32_t r[4];
                LDSM4(r, vaddr + (uint32_t)(nt2 * 16 * APV) * 4 + kkb);
                bf[2 * nt2][0] = r[0]; bf[2 * nt2][1] = r[1];
                bf[2 * nt2 + 1][0] = r[2]; bf[2 * nt2 + 1][1] = r[3];
            }
            LDSM2(bf[6][0], bf[6][1], v6addr + kkb);
#pragma unroll
            for (int nt = 0; nt < 7; nt++)
                MMA_TF32(oacc[nt], af, bf[nt]);
        }
    }

    // epilogue
    float inv0 = 1.f / l0, inv1 = 1.f / l1;
    int r0 = q0 + wq + g;
    uint32_t* o0 = out + (size_t)(b * T + r0) * D + h * HD;
    uint32_t* o1 = o0 + (size_t)8 * D;
#pragma unroll
    for (int nt = 0; nt < 7; nt++) {
        int c = nt * 8 + 2 * t;
        if (c < HD) {
            *(uint2*)(o0 + c) = make_uint2(f2tf32(oacc[nt][0] * inv0),
                                           f2tf32(oacc[nt][1] * inv0));
            *(uint2*)(o1 + c) = make_uint2(f2tf32(oacc[nt][2] * inv1),
                                           f2tf32(oacc[nt][3] * inv1));
        }
    }
}

// ---------------- launch ----------------------------------------------------
extern "C" void kernel_launch(void* const* d_in, const int* in_sizes, int n_in,
                              void* d_out, int out_size) {
    const int* ori            = (const int*)d_in[0];
    const float* x            = (const float*)d_in[1];
    const unsigned char* xm   = (const unsigned char*)d_in[2];
    const float *dwp[4], *dbp[4], *pwp[4], *pbp[4];
    for (int i = 0; i < 4; i++) {
        dwp[i] = (const float*)d_in[3 + 4 * i];
        dbp[i] = (const float*)d_in[4 + 4 * i];
        pwp[i] = (const float*)d_in[5 + 4 * i];
        pbp[i] = (const float*)d_in[6 + 4 * i];
    }
    const float* in_w  = (const float*)d_in[19];
    const float* in_b  = (const float*)d_in[20];
    const float* out_w = (const float*)d_in[21];
    const float* out_b = (const float*)d_in[22];
    const float* ffc_w = (const float*)d_in[23];
    const float* ffc_b = (const float*)d_in[24];
    float* outp = (float*)d_out;

    float *b0, *b1, *b2, *bt, *b1t, *b2t, *qkvp, *wt;
    cudaGetSymbolAddress((void**)&b0,   g_b0);
    cudaGetSymbolAddress((void**)&b1,   g_b1);
    cudaGetSymbolAddress((void**)&b2,   g_b2);
    cudaGetSymbolAddress((void**)&bt,   g_bt);
    cudaGetSymbolAddress((void**)&b1t,  g_b1t);
    cudaGetSymbolAddress((void**)&b2t,  g_b2t);
    cudaGetSymbolAddress((void**)&qkvp, g_qkv);
    cudaGetSymbolAddress((void**)&wt,   g_wt);

    cudaFuncSetAttribute(attn_mma, cudaFuncAttributeMaxDynamicSharedMemorySize, ASM_BYTES);
    cudaFuncSetAttribute(gemm_pipe, cudaFuncAttributeMaxDynamicSharedMemorySize, GSM_BYTES);

    const int DD = D * D;
    float* wtp[4];
    for (int i = 0; i < 4; i++) wtp[i] = wt + i * DD;
    float* wt_in  = wt + 4 * DD;
    float* wt_out = wt_in + D3 * D;
    float* wt_ffc = wt_out + DD;

    int ncvt = 6 * DD + D3 * D;
    cvt_all<<<(ncvt + 255) / 256, 256>>>(pwp[0], pwp[1], pwp[2], pwp[3],
                                         in_w, out_w, ffc_w, (uint32_t*)wt);

    int eblocks  = (BTD + 255) / 256;
    int e4blocks = (BTD / 4 + 255) / 256;
    dim3 gg5((D + GBN - 1) / GBN, BT / GBM);    // (4, 128)
    dim3 ggq((D3 + GBN - 1) / GBN, BT / GBM);   // (12, 128)
    dim3 gga(T / AMQ, B * H);                   // (4, 320)

    posemb_kernel<<<eblocks, 256>>>(ori, x, b0);
    dwconv4_kernel<<<e4blocks, 256>>>(b0, dwp[0], dbp[0], (uint32_t*)bt);
    gemm_pipe<<<gg5, 256, GSM_BYTES>>>(bt, wtp[0], pbp[0], b0, b1, nullptr, D, D, 0);
    dwconv4_kernel<<<e4blocks, 256>>>(b1, dwp[1], dbp[1], (uint32_t*)bt);
    gemm_pipe<<<gg5, 256, GSM_BYTES>>>(bt, wtp[1], pbp[1], b1, b2, nullptr, D, D, 0);
    dwconv4_kernel<<<e4blocks, 256>>>(b2, dwp[2], dbp[2], (uint32_t*)bt);
    gemm_pipe<<<gg5, 256, GSM_BYTES>>>(bt, wtp[2], pbp[2], b2, b0, nullptr, D, D, 0);
    dwconv4_kernel<<<e4blocks, 256>>>(b0, dwp[3], dbp[3], (uint32_t*)bt);
    gemm_pipe<<<gg5, 256, GSM_BYTES>>>(bt, wtp[3], pbp[3], b0, b1, (uint32_t*)b1t, D, D, 1);
    gemm_pipe<<<ggq, 256, GSM_BYTES>>>(b1t, wt_in, in_b, nullptr, qkvp, nullptr, D3, D, 2);
    attn_mma<<<gga, 256, ASM_BYTES>>>(qkvp, xm, (uint32_t*)bt);
    gemm_pipe<<<gg5, 256, GSM_BYTES>>>(bt, wt_out, out_b, b1, b2, (uint32_t*)b2t, D, D, 1);
    gemm_pipe<<<gg5, 256, GSM_BYTES>>>(b2t, wt_ffc, ffc_b, b2, outp, nullptr, D, D, 0);
}